// round 16
// baseline (speedup 1.0000x reference)
#include <cuda_runtime.h>
#include <cuda_bf16.h>

// Closed-form Heisenberg-picture evaluation of the 4-qubit circuit.
//   Cq = cos(pi*x_q), Sq = sin(pi*x_q)
//   ev0 = cos(w2)*cos(w0)*C0 - sin(w2)*S0*S2
//   ev1 = cos(w1)*C1
//   ev2 = cos(w0)*C0*C2
//   ev3 = cos(w3)*ev2*C3 - sin(w3)*S3
// 8 samples per thread, front-batched LDG.128 (MLP=8) to hide DRAM latency.
// Grid fixed at 2 CTAs per SM (296 blocks) for a perfectly balanced single wave.

#define VPT    8     // float4 samples per thread (upper bound; tail predicated)
#define BLOCKS 296   // 148 SMs * 2 CTAs
#define TPB    128

__global__ __launch_bounds__(TPB) void quanv_closed_kernel(
    const float4* __restrict__ x,
    const float* __restrict__ w,
    float4* __restrict__ out,
    int B)
{
    int tid = blockIdx.x * TPB + threadIdx.x;
    const int nt = BLOCKS * TPB;

    // Weight trig: uniform across threads, amortized over VPT samples.
    float cw0, cw1, cw2, sw2, cw3, sw3, t0, t1;
    __sincosf(__ldg(w + 0), &t0,  &cw0);
    __sincosf(__ldg(w + 1), &t1,  &cw1);
    __sincosf(__ldg(w + 2), &sw2, &cw2);
    __sincosf(__ldg(w + 3), &sw3, &cw3);

    // Front-batch VPT independent vector loads (coalesced: stride = nt).
    float4 xv[VPT];
    int idx[VPT];
#pragma unroll
    for (int k = 0; k < VPT; k++) {
        idx[k] = tid + k * nt;
        if (idx[k] < B) xv[k] = __ldg(x + idx[k]);
    }

    const float PI = 3.14159265358979323846f;
#pragma unroll
    for (int k = 0; k < VPT; k++) {
        if (idx[k] >= B) continue;
        float C0, S0, C1, C2, S2, C3, S3, tmp;
        __sincosf(xv[k].x * PI, &S0,  &C0);
        __sincosf(xv[k].y * PI, &tmp, &C1);
        __sincosf(xv[k].z * PI, &S2,  &C2);
        __sincosf(xv[k].w * PI, &S3,  &C3);

        float a   = cw0 * C0;
        float ev1 = cw1 * C1;
        float ev2 = a * C2;
        float ev0 = cw2 * a - sw2 * (S0 * S2);
        float ev3 = cw3 * (ev2 * C3) - sw3 * S3;

        out[idx[k]] = make_float4(ev0, ev1, ev2, ev3);
    }
}

extern "C" void kernel_launch(void* const* d_in, const int* in_sizes, int n_in,
                              void* d_out, int out_size) {
    const float4* x = (const float4*)d_in[0];   // [B, 4] float32
    const float* w  = (const float*)d_in[1];    // [4] float32
    float4* out     = (float4*)d_out;           // [B, 4] float32

    int B = in_sizes[0] / 4;                    // number of samples
    quanv_closed_kernel<<<BLOCKS, TPB>>>(x, w, out, B);
}